// round 2
// baseline (speedup 1.0000x reference)
#include <cuda_runtime.h>
#include <cstdint>

// out[col[e], :] += x[row[e], :]   for e in [0, E)
// x: [N, 128] f32.
// edge_index: [2, E] — int32 on device (JAX x64-disabled downcasts the
// reference's jnp.int64 randint to int32).
//
// Warp-per-edge: lane l handles floats [4l, 4l+4) of the 128-float feature row.
// Gather: one coalesced 512B row read per warp (L2-resident, x = 25.6MB).
// Scatter: vectorized red.global.add.v4.f32 (no-return REDG path), 1 vec4
// atomic per lane per edge -> 16M vec4 reds total instead of 64M scalars.

static constexpr int D = 128;
static constexpr int WARPS_PER_BLOCK = 8;
static constexpr int THREADS = WARPS_PER_BLOCK * 32;

__global__ void __launch_bounds__(THREADS)
mp_scatter_add_kernel(const float* __restrict__ x,
                      const int* __restrict__ edge_index,
                      float* __restrict__ out,
                      int E)
{
    int warp_id = (blockIdx.x * WARPS_PER_BLOCK) + (threadIdx.x >> 5);
    int lane = threadIdx.x & 31;
    if (warp_id >= E) return;

    int src = __ldg(edge_index + warp_id);       // row (source j)
    int dst = __ldg(edge_index + E + warp_id);   // col (target i)

    const float4* xrow = reinterpret_cast<const float4*>(x + (size_t)src * D);
    float4 v = __ldg(xrow + lane);

    float* o = out + (size_t)dst * D + lane * 4;
    asm volatile("red.global.add.v4.f32 [%0], {%1, %2, %3, %4};"
                 :: "l"(o), "f"(v.x), "f"(v.y), "f"(v.z), "f"(v.w)
                 : "memory");
}

extern "C" void kernel_launch(void* const* d_in, const int* in_sizes, int n_in,
                              void* d_out, int out_size)
{
    const float* x = (const float*)d_in[0];
    const int* edge_index = (const int*)d_in[1];
    float* out = (float*)d_out;

    int E = in_sizes[1] / 2;  // edge_index has 2*E elements

    // d_out is poisoned; zero it first (graph-capturable async memset).
    cudaMemsetAsync(out, 0, (size_t)out_size * sizeof(float), 0);

    int blocks = (E + WARPS_PER_BLOCK - 1) / WARPS_PER_BLOCK;
    mp_scatter_add_kernel<<<blocks, THREADS>>>(x, edge_index, out, E);
}